// round 11
// baseline (speedup 1.0000x reference)
#include <cuda_runtime.h>
#include <cuda_bf16.h>
#include <cstdint>

// CrossAttentionModel_20684562497797 — FINAL FORM
//
// Reference math collapses: softmax over a size-1 axis == 1.0 exactly for any
// finite input; mean over heads of ones == 1.0. Output is ones((2048,2048))
// independent of all inputs -> only mandatory work: write 16 MiB of 1.0f.
//
// R9 conclusion: four structurally different fills (grid-stride STG, TMA bulk,
// flat 2-store, unroll-8) all land at 5.5-6.4us kernel with L2 ~26%, issue
// 4-15%, occ 10-73% -> no programmable resource is binding. The ~5.5us floor
// is ~1.3us mandatory L2-port store time (16.7MB / ~6300 B/cyc) plus fixed
// ramp/launch overhead invariant to kernel structure.
//
// This is the empirically fastest structure (R7): one wave, 2048 CTAs x 256
// threads, exactly 2 coalesced STG.128 per thread (1M float4 = exact cover),
// tail predicated into the same kernel so the graph is always one node.

static constexpr int THREADS = 256;
static constexpr int V4_PER_CTA = THREADS * 2;  // 512 float4 = 8 KiB per CTA

__global__ __launch_bounds__(THREADS)
void fill_ones_kernel(float4* __restrict__ out4, int n4,
                      float* __restrict__ out, int n_total) {
    const float4 one4 = make_float4(1.0f, 1.0f, 1.0f, 1.0f);
    int base = blockIdx.x * V4_PER_CTA + threadIdx.x;

    // Two independent, coalesced 128-bit stores; guards uniformly true for
    // the real shape (n4 = 1M, grid = 2048) and predicated-out for free.
    int i0 = base;
    int i1 = base + THREADS;
    if (i0 < n4) out4[i0] = one4;
    if (i1 < n4) out4[i1] = one4;

    // Scalar tail for out_size % 4 != 0 (never hit for 2048x2048); keeps the
    // captured graph a single kernel node for any out_size.
    if (blockIdx.x == 0) {
        int t = n4 * 4 + threadIdx.x;
        if (t < n_total) out[t] = 1.0f;
    }
}

extern "C" void kernel_launch(void* const* d_in, const int* in_sizes, int n_in,
                              void* d_out, int out_size) {
    (void)d_in; (void)in_sizes; (void)n_in;

    float* out = (float*)d_out;
    int n4 = out_size / 4;                               // 1,048,576
    int blocks = (n4 + V4_PER_CTA - 1) / V4_PER_CTA;     // 2048
    if (blocks < 1) blocks = 1;

    fill_ones_kernel<<<blocks, THREADS>>>((float4*)out, n4, out, out_size);
}

// round 14
// speedup vs baseline: 1.0040x; 1.0040x over previous
#include <cuda_runtime.h>
#include <cuda_bf16.h>
#include <cstdint>

// CrossAttentionModel_20684562497797 — FINAL
//
// Reference math collapses: softmax over a size-1 axis == 1.0 exactly for any
// finite input; mean over heads of ones == 1.0. Output is ones((2048,2048))
// independent of all inputs -> only mandatory work: write 16 MiB of 1.0f.
//
// Landscape fully swept (R5-R11): grid-stride STG, TMA bulk, flat 2-store,
// unroll-8, grids 512..2048 -> kernel dur pinned at 5.55-5.8us with L2 ~26%,
// issue 4-15%, occ 10-73%. No programmable resource binds; the floor is
// ~1.3us mandatory L2-port store time (16.7MB / ~6300 B/cyc) + fixed
// launch/ramp overhead. e2e noise is +-1-2us; best measured e2e (6.624us)
// came from this exact configuration: 512 CTAs x 256 thr x 8 static STG.128.

static constexpr int THREADS = 256;
static constexpr int V4_PER_THREAD = 8;
static constexpr int V4_PER_CTA = THREADS * V4_PER_THREAD;  // 2048 float4 = 32 KiB

__global__ __launch_bounds__(THREADS)
void fill_ones_kernel(float4* __restrict__ out4, int n4,
                      float* __restrict__ out, int n_total) {
    const float4 one4 = make_float4(1.0f, 1.0f, 1.0f, 1.0f);
    int base = blockIdx.x * V4_PER_CTA + threadIdx.x;

    // 8 independent coalesced STG.128s, statically unrolled (front-batched by
    // ptxas -> MLP=8/thread). Guards uniformly true for the real shape
    // (n4 = 1M, grid = 512) and predicated out for free.
    #pragma unroll
    for (int j = 0; j < V4_PER_THREAD; j++) {
        int i = base + j * THREADS;
        if (i < n4) out4[i] = one4;
    }

    // Scalar tail for out_size % 4 != 0 (never hit for 2048x2048); keeps the
    // captured graph a single kernel node for any out_size.
    if (blockIdx.x == 0) {
        int t = n4 * 4 + threadIdx.x;
        if (t < n_total) out[t] = 1.0f;
    }
}

extern "C" void kernel_launch(void* const* d_in, const int* in_sizes, int n_in,
                              void* d_out, int out_size) {
    (void)d_in; (void)in_sizes; (void)n_in;

    float* out = (float*)d_out;
    int n4 = out_size / 4;                               // 1,048,576
    int blocks = (n4 + V4_PER_CTA - 1) / V4_PER_CTA;     // 512
    if (blocks < 1) blocks = 1;

    fill_ones_kernel<<<blocks, THREADS>>>((float4*)out, n4, out, out_size);
}